// round 14
// baseline (speedup 1.0000x reference)
#include <cuda_runtime.h>
#include <cuda_pipeline.h>

// Sobel_16724602651101 — R13
// x: (16, 3, 512, 512) fp32 -> out: [magnitude | angle] each (16,512,512) fp32.
//
// R11 skeleton (cp.async smem staging, monolithic wait, ONE barrier) plus:
//  - edge-halo handled by predicated register fixup in compute (no smem
//    patch phase, no second barrier for edge blocks)
//  - __launch_bounds__(256,5): reg cap 51 -> 5 blocks/SM for load overlap
// Numeric trees frozen from the R1-R12 lineage (R1 grouping, exact
// power-of-two deferred scaling, sqrt.approx + __fdividef; rel_err 1.0849e-7).

#define BATCH 16
#define CH 3
#define HH 512
#define WW 512
#define HW (HH * WW)

#define TILE_W 128
#define TILE_H 16
#define LH 18            // halo rows per channel
#define LPITCH 136       // halo cols: j <-> global col bx0-4+j ; used j = 3..132

#define EPS64 (64.0f * 1e-9f)
#define TINY8 (8.0f * 1e-9f)

__device__ __forceinline__ float fsqrt_approx(float a)
{
    float r;
    asm("sqrt.approx.f32 %0, %1;" : "=f"(r) : "f"(a));
    return r;
}

__global__ __launch_bounds__(256, 5)
void sobel_kernel(const float* __restrict__ x, float* __restrict__ out)
{
    __shared__ __align__(16) float s[CH][LH][LPITCH];

    const int bx0 = blockIdx.x * TILE_W;
    const int by0 = blockIdx.y * TILE_H;
    const int b   = blockIdx.z;
    const int tid = threadIdx.x;
    const int lane = tid & 31;
    const int wid  = tid >> 5;

    const float* __restrict__ xb = x + (size_t)b * CH * HW;

    // lane-predicated edge fixups (replicate padding), resolved in registers
    const bool fixL = (bx0 == 0) && (lane == 0);
    const bool fixR = (bx0 + TILE_W == WW) && (lane == 31);

    // ---- load phase: warp=row, lane=16B group; no div/mod ----
    const int col_a = min(max(bx0 - 4 + 4 * lane, 0), WW - 4);
    const int col_b = min(max(bx0 + 124 + 4 * lane, 0), WW - 4);

    #pragma unroll
    for (int c = 0; c < CH; c++) {
        const float* __restrict__ xc = xb + c * HW;
        #pragma unroll
        for (int k = 0; k < 3; k++) {
            const int r = wid + 8 * k;            // 0..23; valid r<18
            if (k < 2 || wid < 2) {
                const int gr = min(max(by0 - 1 + r, 0), HH - 1);
                const float* __restrict__ rp = xc + gr * WW;
                __pipeline_memcpy_async(&s[c][r][4 * lane], rp + col_a, 16);
                if (lane < 2)
                    __pipeline_memcpy_async(&s[c][r][128 + 4 * lane], rp + col_b, 16);
            }
        }
    }
    __pipeline_commit();
    __pipeline_wait_prior(0);
    __syncthreads();

    // ---- compute: 4 cols x 2 rows per thread ----
    const int lc = 4 * lane;                      // window local cols lc+3..lc+8
    const int wy = wid;                           // out rows by0+2wy, +2wy+1

    float bm[2][4], bgx[2][4], bgy[2][4];

    #pragma unroll
    for (int c = 0; c < CH; c++) {
        // 4 input rows (local 2wy..2wy+3) x 6 cols, conflict-free LDS
        float w[4][6];
        #pragma unroll
        for (int i = 0; i < 4; i++) {
            const float* __restrict__ row = &s[c][2 * wy + i][0];
            float2 va = *(const float2*)(row + lc + 2);   // cols lc+2, lc+3
            float4 v  = *(const float4*)(row + lc + 4);   // cols lc+4..lc+7
            float2 vb = *(const float2*)(row + lc + 8);   // cols lc+8, lc+9
            w[i][0] = va.y;
            w[i][1] = v.x; w[i][2] = v.y; w[i][3] = v.z; w[i][4] = v.w;
            w[i][5] = vb.x;
            // replicate-padding fixups (predicated, no smem patch needed)
            if (fixL) w[i][0] = w[i][1];          // col -1 := col 0
            if (fixR) w[i][5] = w[i][4];          // col 512 := col 511
        }

        // horizontal diffs once per input row (rows 1,2 shared by both outputs)
        float dr[4][4];
        #pragma unroll
        for (int i = 0; i < 4; i++)
            #pragma unroll
            for (int p = 0; p < 4; p++) dr[i][p] = w[i][p + 2] - w[i][p];

        // vertical diffs per output row
        float vd[2][6];
        #pragma unroll
        for (int j = 0; j < 6; j++) { vd[0][j] = w[2][j] - w[0][j];
                                      vd[1][j] = w[3][j] - w[1][j]; }

        #pragma unroll
        for (int rr = 0; rr < 2; rr++) {
            #pragma unroll
            for (int p = 0; p < 4; p++) {
                // 8x-scaled gx/gy, R1's exact grouping
                float gx = dr[rr][p] + 2.0f * dr[rr + 1][p] + dr[rr + 2][p];
                float gy = vd[rr][p] + 2.0f * vd[rr][p + 1] + vd[rr][p + 2];
                float m  = gx * gx + gy * gy + EPS64;      // 64x-scaled
                if (c == 0) {
                    bm[rr][p] = m; bgx[rr][p] = gx; bgy[rr][p] = gy;
                } else if (m > bm[rr][p]) {   // strict >: first-occurrence argmax
                    bm[rr][p] = m; bgx[rr][p] = gx; bgy[rr][p] = gy;
                }
            }
        }
    }

    const size_t oang = (size_t)BATCH * HW;

    #pragma unroll
    for (int rr = 0; rr < 2; rr++) {
        float4 mag, ang;
        mag.x = fsqrt_approx(bm[rr][0]) * 0.125f;   // == sqrt(m)/8 bitwise
        mag.y = fsqrt_approx(bm[rr][1]) * 0.125f;
        mag.z = fsqrt_approx(bm[rr][2]) * 0.125f;
        mag.w = fsqrt_approx(bm[rr][3]) * 0.125f;

        float y0 = (bgy[rr][0] == 0.f) ? TINY8 : bgy[rr][0];
        float y1 = (bgy[rr][1] == 0.f) ? TINY8 : bgy[rr][1];
        float y2 = (bgy[rr][2] == 0.f) ? TINY8 : bgy[rr][2];
        float y3 = (bgy[rr][3] == 0.f) ? TINY8 : bgy[rr][3];
        ang.x = fminf(fmaxf(__fdividef(bgx[rr][0], y0), -10.f), 10.f);
        ang.y = fminf(fmaxf(__fdividef(bgx[rr][1], y1), -10.f), 10.f);
        ang.z = fminf(fmaxf(__fdividef(bgx[rr][2], y2), -10.f), 10.f);
        ang.w = fminf(fmaxf(__fdividef(bgx[rr][3], y3), -10.f), 10.f);

        const size_t o = (size_t)b * HW + (size_t)(by0 + 2 * wy + rr) * WW + (bx0 + lc);
        *(float4*)(out + o)        = mag;
        *(float4*)(out + oang + o) = ang;
    }
}

extern "C" void kernel_launch(void* const* d_in, const int* in_sizes, int n_in,
                              void* d_out, int out_size)
{
    const float* x = (const float*)d_in[0];
    float* out = (float*)d_out;

    dim3 block(256, 1, 1);
    dim3 grid(WW / TILE_W, HH / TILE_H, BATCH);   // (4, 32, 16) = 2048 blocks
    sobel_kernel<<<grid, block>>>(x, out);
}

// round 15
// speedup vs baseline: 1.0977x; 1.0977x over previous
#include <cuda_runtime.h>
#include <cuda_pipeline.h>

// Sobel_16724602651101 — R14
// x: (16, 3, 512, 512) fp32 -> out: [magnitude | angle] each (16,512,512) fp32.
//
// R11 skeleton (cp.async smem staging, lean warp-structured load indexing)
// with two isolated fixes:
//  - predicated register edge fixup (no smem patch phase / second barrier)
//    at NATURAL register count (no cap -> no spills)
//  - two-stage channel pipeline: group A = ch0, group B = ch1+ch2;
//    compute ch0 overlaps ch1/2 loads. Exactly 2 barriers.
// Numeric trees frozen from the R1-R13 lineage (R1 grouping, exact
// power-of-two deferred scaling, sqrt.approx + __fdividef; rel_err 1.0849e-7).

#define BATCH 16
#define CH 3
#define HH 512
#define WW 512
#define HW (HH * WW)

#define TILE_W 128
#define TILE_H 16
#define LH 18            // halo rows per channel
#define LPITCH 136       // halo cols: j <-> global col bx0-4+j ; used j = 3..132

#define EPS64 (64.0f * 1e-9f)
#define TINY8 (8.0f * 1e-9f)

__device__ __forceinline__ float fsqrt_approx(float a)
{
    float r;
    asm("sqrt.approx.f32 %0, %1;" : "=f"(r) : "f"(a));
    return r;
}

// accumulate one channel from its smem plane into the per-thread argmax state
template <bool FIRST>
__device__ __forceinline__ void compute_channel(
    const float (*sc)[LPITCH], int lc, int wy, bool fixL, bool fixR,
    float bm[2][4], float bgx[2][4], float bgy[2][4])
{
    // 4 input rows (local 2wy..2wy+3) x 6 cols, conflict-free LDS
    float w[4][6];
    #pragma unroll
    for (int i = 0; i < 4; i++) {
        const float* __restrict__ row = &sc[2 * wy + i][0];
        float2 va = *(const float2*)(row + lc + 2);   // cols lc+2, lc+3
        float4 v  = *(const float4*)(row + lc + 4);   // cols lc+4..lc+7
        float2 vb = *(const float2*)(row + lc + 8);   // cols lc+8, lc+9
        w[i][0] = fixL ? v.x : va.y;                  // replicate pad: col -1 := col 0
        w[i][1] = v.x; w[i][2] = v.y; w[i][3] = v.z; w[i][4] = v.w;
        w[i][5] = fixR ? v.w : vb.x;                  // col 512 := col 511
    }

    // horizontal diffs once per input row (rows 1,2 shared by both outputs)
    float dr[4][4];
    #pragma unroll
    for (int i = 0; i < 4; i++)
        #pragma unroll
        for (int p = 0; p < 4; p++) dr[i][p] = w[i][p + 2] - w[i][p];

    // vertical diffs per output row
    float vd[2][6];
    #pragma unroll
    for (int j = 0; j < 6; j++) { vd[0][j] = w[2][j] - w[0][j];
                                  vd[1][j] = w[3][j] - w[1][j]; }

    #pragma unroll
    for (int rr = 0; rr < 2; rr++) {
        #pragma unroll
        for (int p = 0; p < 4; p++) {
            // 8x-scaled gx/gy, R1's exact grouping
            float gx = dr[rr][p] + 2.0f * dr[rr + 1][p] + dr[rr + 2][p];
            float gy = vd[rr][p] + 2.0f * vd[rr][p + 1] + vd[rr][p + 2];
            float m  = gx * gx + gy * gy + EPS64;      // 64x-scaled
            if (FIRST) {
                bm[rr][p] = m; bgx[rr][p] = gx; bgy[rr][p] = gy;
            } else if (m > bm[rr][p]) {   // strict >: first-occurrence argmax
                bm[rr][p] = m; bgx[rr][p] = gx; bgy[rr][p] = gy;
            }
        }
    }
}

__global__ __launch_bounds__(256, 4)
void sobel_kernel(const float* __restrict__ x, float* __restrict__ out)
{
    __shared__ __align__(16) float s[CH][LH][LPITCH];

    const int bx0 = blockIdx.x * TILE_W;
    const int by0 = blockIdx.y * TILE_H;
    const int b   = blockIdx.z;
    const int tid = threadIdx.x;
    const int lane = tid & 31;
    const int wid  = tid >> 5;

    const float* __restrict__ xb = x + (size_t)b * CH * HW;

    const bool fixL = (bx0 == 0) && (lane == 0);
    const bool fixR = (bx0 + TILE_W == WW) && (lane == 31);

    // ---- load phase: warp=row, lane=16B group; no div/mod ----
    const int col_a = min(max(bx0 - 4 + 4 * lane, 0), WW - 4);
    const int col_b = min(max(bx0 + 124 + 4 * lane, 0), WW - 4);

    // stage A: channel 0
    {
        const float* __restrict__ xc = xb;
        #pragma unroll
        for (int k = 0; k < 3; k++) {
            const int r = wid + 8 * k;
            if (k < 2 || wid < 2) {
                const int gr = min(max(by0 - 1 + r, 0), HH - 1);
                const float* __restrict__ rp = xc + gr * WW;
                __pipeline_memcpy_async(&s[0][r][4 * lane], rp + col_a, 16);
                if (lane < 2)
                    __pipeline_memcpy_async(&s[0][r][128 + 4 * lane], rp + col_b, 16);
            }
        }
    }
    __pipeline_commit();

    // stage B: channels 1, 2
    #pragma unroll
    for (int c = 1; c < CH; c++) {
        const float* __restrict__ xc = xb + c * HW;
        #pragma unroll
        for (int k = 0; k < 3; k++) {
            const int r = wid + 8 * k;
            if (k < 2 || wid < 2) {
                const int gr = min(max(by0 - 1 + r, 0), HH - 1);
                const float* __restrict__ rp = xc + gr * WW;
                __pipeline_memcpy_async(&s[c][r][4 * lane], rp + col_a, 16);
                if (lane < 2)
                    __pipeline_memcpy_async(&s[c][r][128 + 4 * lane], rp + col_b, 16);
            }
        }
    }
    __pipeline_commit();

    const int lc = 4 * lane;                      // window local cols lc+3..lc+8
    const int wy = wid;                           // out rows by0+2wy, +2wy+1

    float bm[2][4], bgx[2][4], bgy[2][4];

    // compute ch0 while ch1/ch2 LDGSTS are still in flight
    __pipeline_wait_prior(1);
    __syncthreads();
    compute_channel<true>(s[0], lc, wy, fixL, fixR, bm, bgx, bgy);

    // then the remaining channels
    __pipeline_wait_prior(0);
    __syncthreads();
    compute_channel<false>(s[1], lc, wy, fixL, fixR, bm, bgx, bgy);
    compute_channel<false>(s[2], lc, wy, fixL, fixR, bm, bgx, bgy);

    const size_t oang = (size_t)BATCH * HW;

    #pragma unroll
    for (int rr = 0; rr < 2; rr++) {
        float4 mag, ang;
        mag.x = fsqrt_approx(bm[rr][0]) * 0.125f;   // == sqrt(m)/8 bitwise
        mag.y = fsqrt_approx(bm[rr][1]) * 0.125f;
        mag.z = fsqrt_approx(bm[rr][2]) * 0.125f;
        mag.w = fsqrt_approx(bm[rr][3]) * 0.125f;

        float y0 = (bgy[rr][0] == 0.f) ? TINY8 : bgy[rr][0];
        float y1 = (bgy[rr][1] == 0.f) ? TINY8 : bgy[rr][1];
        float y2 = (bgy[rr][2] == 0.f) ? TINY8 : bgy[rr][2];
        float y3 = (bgy[rr][3] == 0.f) ? TINY8 : bgy[rr][3];
        ang.x = fminf(fmaxf(__fdividef(bgx[rr][0], y0), -10.f), 10.f);
        ang.y = fminf(fmaxf(__fdividef(bgx[rr][1], y1), -10.f), 10.f);
        ang.z = fminf(fmaxf(__fdividef(bgx[rr][2], y2), -10.f), 10.f);
        ang.w = fminf(fmaxf(__fdividef(bgx[rr][3], y3), -10.f), 10.f);

        const size_t o = (size_t)b * HW + (size_t)(by0 + 2 * wy + rr) * WW + (bx0 + lc);
        *(float4*)(out + o)        = mag;
        *(float4*)(out + oang + o) = ang;
    }
}

extern "C" void kernel_launch(void* const* d_in, const int* in_sizes, int n_in,
                              void* d_out, int out_size)
{
    const float* x = (const float*)d_in[0];
    float* out = (float*)d_out;

    dim3 block(256, 1, 1);
    dim3 grid(WW / TILE_W, HH / TILE_H, BATCH);   // (4, 32, 16) = 2048 blocks
    sobel_kernel<<<grid, block>>>(x, out);
}